// round 9
// baseline (speedup 1.0000x reference)
#include <cuda_runtime.h>
#include <cstdint>

// out[s, r, j] = in[r, idx[s] + j]
// in: (131072, 512) fp32 ; idx: (16,) int32 in [0,448) ; out: (16, 131072, 64) fp32
//
// Persistent double-buffered variant: 1216 CTAs (~8/SM) grid-stride over
// 4-row groups. Per iteration: stage next group's rows into buffer B^1
// (predicated LDG.128, sector-exact coverage) WHILE emitting current group
// from buffer B (LDS + STG.128, 256B-contiguous full-sector writes), then
// one barrier. Keeps read+write streams concurrently in flight per SM and
// amortizes idx/coverage setup over ~27 groups per CTA.

#define FEAT 512
#define NUM_SLICES 16
#define SLICE_LEN 64
#define RPC 4            // rows per group (n_rows % RPC == 0)
#define GRID 1216        // ~8 CTAs/SM on 148-152 SMs

__global__ __launch_bounds__(256) void fuse_slice_kernel(
    const float* __restrict__ in,
    const int* __restrict__ idx,
    float* __restrict__ out,
    int n_rows)
{
    __shared__ float row[2][RPC][FEAT];
    __shared__ int sidx[NUM_SLICES];

    const int t = threadIdx.x;

    if (t < NUM_SLICES) sidx[t] = idx[t];
    __syncthreads();

    // Staging assignment: chunk c = t + 256*i -> row k = (t>>7) + 2*i,
    // float4-index c4 = t&127. Coverage depends only on c4.
    // Chunk [col, col+3] intersects slice [b, b+63] iff col-b in [-3, 63].
    const int c4  = t & 127;
    const int col = c4 << 2;
    const int k0  = t >> 7;

    bool need = false;
    #pragma unroll
    for (int s = 0; s < NUM_SLICES; s++) {
        const int d = col - sidx[s];
        need |= ((unsigned)(d + 3) < (unsigned)(SLICE_LEN + 3));
    }

    // Emit assignment: thread t -> slice s = t>>4, quad v = (t&15)*4.
    const int s = t >> 4;
    const int v = (t & 15) << 2;
    const int base = sidx[s] + v;

    const int n_groups = n_rows / RPC;

    // Prologue: stage first group into buffer 0.
    int g = blockIdx.x;
    if (need) {
        const size_t r0 = (size_t)g * RPC;
        #pragma unroll
        for (int i = 0; i < 2; i++) {
            const int k = k0 + 2 * i;
            reinterpret_cast<float4*>(row[0][k])[c4] =
                reinterpret_cast<const float4*>(in + (r0 + k) * FEAT)[c4];
        }
    }

    int buf = 0;
    while (g < n_groups) {
        const int gn = g + GRID;
        __syncthreads();   // buffer `buf` fully staged; previous emit done

        // Stage NEXT group into the other buffer (overlaps with emit below).
        if (gn < n_groups && need) {
            const size_t r0n = (size_t)gn * RPC;
            #pragma unroll
            for (int i = 0; i < 2; i++) {
                const int k = k0 + 2 * i;
                reinterpret_cast<float4*>(row[buf ^ 1][k])[c4] =
                    reinterpret_cast<const float4*>(in + (r0n + k) * FEAT)[c4];
            }
        }

        // Emit current group from `buf`.
        {
            const size_t r0 = (size_t)g * RPC;
            #pragma unroll
            for (int k = 0; k < RPC; k++) {
                float4 val;
                val.x = row[buf][k][base + 0];
                val.y = row[buf][k][base + 1];
                val.z = row[buf][k][base + 2];
                val.w = row[buf][k][base + 3];

                const size_t o = (((size_t)s * n_rows + (r0 + k)) << 6) + (size_t)v;
                *reinterpret_cast<float4*>(out + o) = val;
            }
        }

        buf ^= 1;
        g = gn;
    }
}

extern "C" void kernel_launch(void* const* d_in, const int* in_sizes, int n_in,
                              void* d_out, int out_size)
{
    const float* in  = (const float*)d_in[0];
    const int*   idx = (const int*)d_in[1];
    float*       out = (float*)d_out;

    const int n_rows = in_sizes[0] / FEAT;   // 131072, multiple of RPC

    fuse_slice_kernel<<<GRID, 256>>>(in, idx, out, n_rows);
}

// round 10
// speedup vs baseline: 1.1971x; 1.1971x over previous
#include <cuda_runtime.h>
#include <cstdint>

// out[s, r, j] = in[r, idx[s] + j]
// in: (131072, 512) fp32 ; idx: (16,) int32 in [0,448) ; out: (16, 131072, 64) fp32
//
// FINAL (locked after R4-R9 sweep): 4 rows/CTA staged in smem via 2
// front-batched LDG.128/thread, predicated on slice coverage (reads are
// sector-exact: ~8% of row bytes never fetched). Emit: thread t -> slice
// s=t>>4, quad v=(t&15)*4, one STG.128 per row; each warp streams contiguous
// 256B full-sector aligned segments.
//
// Measured design space:
//   RPC=2: 118.5us  RPC=4: 117.9us  RPC=8: 119.0us
//   __ldcs/__stcs: neutral.  persistent+double-buffer: 142us (barrier
//   serializes staging-load latency; cross-CTA overlap is strictly better).
// Traffic = 512MB write + ~220MB covered read at the ~6.3TB/s (79-80% DRAM)
// mixed-R/W achieved ceiling -> ~116us kernel; this config sits on it.

#define FEAT 512
#define NUM_SLICES 16
#define SLICE_LEN 64
#define RPC 4   // rows per CTA (n_rows % RPC == 0 for this problem)

__global__ __launch_bounds__(256) void fuse_slice_kernel(
    const float* __restrict__ in,
    const int* __restrict__ idx,
    float* __restrict__ out,
    int n_rows)
{
    __shared__ float row[RPC][FEAT];
    __shared__ int sidx[NUM_SLICES];

    const int t = threadIdx.x;
    const size_t r0 = (size_t)blockIdx.x * RPC;

    if (t < NUM_SLICES) sidx[t] = idx[t];
    __syncthreads();

    // ---- staging: 512 float4 chunks per CTA, 2 per thread.
    // chunk c = t + 256*i -> row k = (t>>7) + 2*i, float4-index c4 = t&127.
    // Coverage predicate depends only on c4 -> computed once per thread.
    // Chunk [col, col+3] intersects slice [b, b+63] iff col-b in [-3, 63].
    const int c4  = t & 127;
    const int col = c4 << 2;

    bool need = false;
    #pragma unroll
    for (int s = 0; s < NUM_SLICES; s++) {
        const int d = col - sidx[s];
        need |= ((unsigned)(d + 3) < (unsigned)(SLICE_LEN + 3));
    }

    const int k0 = t >> 7;  // 0 or 1; second chunk is row k0+2
    if (need) {
        #pragma unroll
        for (int i = 0; i < 2; i++) {
            const int k = k0 + 2 * i;
            reinterpret_cast<float4*>(row[k])[c4] =
                reinterpret_cast<const float4*>(in + (r0 + k) * FEAT)[c4];
        }
    }
    __syncthreads();

    // ---- emit: thread t -> slice s, quad v; one float4 store per row.
    const int s = t >> 4;
    const int v = (t & 15) << 2;
    const int base = sidx[s] + v;

    #pragma unroll
    for (int k = 0; k < RPC; k++) {
        float4 val;
        val.x = row[k][base + 0];
        val.y = row[k][base + 1];
        val.z = row[k][base + 2];
        val.w = row[k][base + 3];

        const size_t o = (((size_t)s * n_rows + (r0 + k)) << 6) + (size_t)v;
        *reinterpret_cast<float4*>(out + o) = val;
    }
}

extern "C" void kernel_launch(void* const* d_in, const int* in_sizes, int n_in,
                              void* d_out, int out_size)
{
    const float* in  = (const float*)d_in[0];
    const int*   idx = (const int*)d_in[1];
    float*       out = (float*)d_out;

    const int n_rows = in_sizes[0] / FEAT;   // 131072, multiple of RPC

    fuse_slice_kernel<<<n_rows / RPC, 256>>>(in, idx, out, n_rows);
}